// round 5
// baseline (speedup 1.0000x reference)
#include <cuda_runtime.h>
#include <cuda_fp16.h>
#include <mma.h>

using namespace nvcuda;

#define Bsz  4096
#define Nseq 512
#define Csz  512
#define PHId 128
#define H1d  512
#define H2d  256

// Scratch (__device__ globals; no allocations allowed)
__device__ __half g_hist [Bsz * Csz];    // 4 MB  per-row label histogram (fp16, exact)
__device__ __half g_u    [Bsz * PHId];   // 1 MB  centered u (bias folded into b1_eff)
__device__ __half g_h1   [Bsz * H1d];    // 4 MB
__device__ float  g_part [4 * Bsz];      // partial dots (deterministic reduce)
__device__ __half g_Wphi [Csz * PHId];
__device__ __half g_W1   [PHId * H1d];
__device__ __half g_W2   [H1d * H2d];
__device__ float  g_b1eff[H1d];          // b1 + 512 * (b_phi @ W1), exact fp32

// ---------------------------------------------------------------------------
// cp.async helpers (LDGSTS, 16B)
// ---------------------------------------------------------------------------
__device__ __forceinline__ void cp_async16(void* smem, const void* gmem) {
    unsigned s = (unsigned)__cvta_generic_to_shared(smem);
    asm volatile("cp.async.cg.shared.global [%0], [%1], 16;\n" :: "r"(s), "l"(gmem));
}
__device__ __forceinline__ void cp_commit() {
    asm volatile("cp.async.commit_group;\n");
}
template <int NN>
__device__ __forceinline__ void cp_wait() {
    asm volatile("cp.async.wait_group %0;\n" :: "n"(NN));
}

// ---------------------------------------------------------------------------
// Prep kernel: blocks [0,512): per-row histograms (8 rows/block, smem atomics)
//              blocks [512,576): fp32->fp16 weight conversion
//              block  512 also: b1_eff = b1 + 512*(b_phi @ W1) in fp32
// ---------------------------------------------------------------------------
__global__ void __launch_bounds__(256) prep_kernel(const int* __restrict__ x,
                                                   const float* __restrict__ Wphi,
                                                   const float* __restrict__ W1,
                                                   const float* __restrict__ W2,
                                                   const float* __restrict__ bphi,
                                                   const float* __restrict__ b1)
{
    const int tid = threadIdx.x;
    if (blockIdx.x < 512) {
        __shared__ int hs[8 * Csz];   // 16 KB
#pragma unroll
        for (int i = 0; i < 16; i++) hs[tid + i * 256] = 0;
        __syncthreads();

        const int warp = tid >> 5, lane = tid & 31;
        const int row = blockIdx.x * 8 + warp;
        const int* xr = x + (size_t)row * Nseq;
#pragma unroll 4
        for (int j = lane; j < Nseq; j += 32) atomicAdd(&hs[warp * Csz + xr[j]], 1);
        __syncthreads();

#pragma unroll
        for (int e = tid; e < 8 * Csz; e += 256) {
            const int r = e >> 9, c = e & (Csz - 1);
            g_hist[(size_t)(blockIdx.x * 8 + r) * Csz + c] =
                __float2half((float)hs[r * Csz + c]);
        }
    } else {
        const int cb = blockIdx.x - 512;               // 0..63
        const int t = cb * 256 + tid;
        const int stride = 64 * 256;
        for (int i = t; i < Csz * PHId; i += stride) g_Wphi[i] = __float2half(Wphi[i]);
        for (int i = t; i < PHId * H1d; i += stride) g_W1[i]   = __float2half(W1[i]);
        for (int i = t; i < H1d * H2d;  i += stride) g_W2[i]   = __float2half(W2[i]);
        if (cb == 0) {
#pragma unroll
            for (int o = tid; o < H1d; o += 256) {
                float s = 0.f;
                for (int k = 0; k < PHId; k++) s = fmaf(bphi[k], W1[k * H1d + o], s);
                g_b1eff[o] = b1[o] + (float)Nseq * s;
            }
        }
    }
}

// ---------------------------------------------------------------------------
// Pipelined fp16 tensor-core GEMM, fp32 accumulate.
// BN=64, BK=32, 256 threads = 8 warps in 2(row) x 4(col) groups.
// Warp tile: (BM/2) x 16, i.e. FR = BM/32 row fragments, 1 col fragment.
// 3-stage cp.async pipeline. Optional fused W3-dot epilogue (writes g_part).
// ---------------------------------------------------------------------------
template <int BM, bool HAS_BIAS, bool RELU, bool FUSED>
__global__ void __launch_bounds__(256) gemm_tc(const __half* __restrict__ A,
                                               const __half* __restrict__ B,
                                               const float* __restrict__ bias,
                                               const float* __restrict__ W3,
                                               __half* __restrict__ C,
                                               int M, int N, int K)
{
    constexpr int BN = 64, BK = 32, T = 256;
    constexpr int FR = BM / 32;          // 16x16 row frags per warp (1 or 2)
    __shared__ __align__(16) union USM {
        struct { __half A[3][BM][BK + 8]; __half B[3][BK][BN + 8]; } in;
        float Cs[BM][BN + 4];
    } sm;
    __shared__ float w3s[BN];
    __shared__ float bs[BN];
    __shared__ float sp[BM][8];

    const int tid  = threadIdx.x;
    const int warp = tid >> 5;
    const int wr   = warp & 1;      // row warp-group (0..1), covers BM/2 rows
    const int wc   = warp >> 1;     // col warp-group (0..3), 16 cols each
    const int rowBase = blockIdx.y * BM;
    const int colBase = blockIdx.x * BN;

    if (FUSED && tid < BN) {
        w3s[tid] = W3[colBase + tid];
        bs[tid]  = bias[colBase + tid];
    }

    // loader maps (16B chunks): A tile BM x 32 -> BM*4 chunks; B 32x64 -> 256
    const int ar = tid >> 2, ac = (tid & 3) << 3;
    const int br = tid >> 3, bc = (tid & 7) << 3;

    const __half* Ag = A + (size_t)rowBase * K;
    const __half* Bg = B + colBase;

    auto load_tile = [&](int s, int kt) {
        const __half* Ak = Ag + kt * BK;
        if (BM == 64 || tid < BM * 4)
            cp_async16(&sm.in.A[s][ar][ac], Ak + (size_t)ar * K + ac);
        const __half* Bk = Bg + (size_t)(kt * BK) * N;
        cp_async16(&sm.in.B[s][br][bc], Bk + (size_t)br * N + bc);
    };

    wmma::fragment<wmma::accumulator, 16, 16, 16, float> acc[FR];
#pragma unroll
    for (int i = 0; i < FR; i++) wmma::fill_fragment(acc[i], 0.f);

    const int KT = K / BK;
    load_tile(0, 0); cp_commit();
    load_tile(1, 1); cp_commit();

    for (int kt = 0; kt < KT; kt++) {
        if (kt + 2 < KT) load_tile((kt + 2) % 3, kt + 2);
        cp_commit();                 // possibly-empty group keeps counting uniform
        cp_wait<2>();
        __syncthreads();

        const int s = kt % 3;
#pragma unroll
        for (int kk = 0; kk < 2; kk++) {
            wmma::fragment<wmma::matrix_a, 16, 16, 16, __half, wmma::row_major> af[FR];
            wmma::fragment<wmma::matrix_b, 16, 16, 16, __half, wmma::row_major> bf;
#pragma unroll
            for (int i = 0; i < FR; i++)
                wmma::load_matrix_sync(af[i],
                    &sm.in.A[s][wr * (BM / 2) + i * 16][kk * 16], BK + 8);
            wmma::load_matrix_sync(bf, &sm.in.B[s][kk * 16][wc * 16], BN + 8);
#pragma unroll
            for (int i = 0; i < FR; i++)
                wmma::mma_sync(acc[i], af[i], bf, acc[i]);
        }
        __syncthreads();
    }

    // spill accumulators to smem (safe: all cp.async drained, all warps synced)
#pragma unroll
    for (int i = 0; i < FR; i++)
        wmma::store_matrix_sync(&sm.Cs[wr * (BM / 2) + i * 16][wc * 16],
                                acc[i], BN + 4, wmma::mem_row_major);
    __syncthreads();

    if (!FUSED) {
        // 8 cols per thread -> one STG.128 of 8 halves
#pragma unroll
        for (int e = tid; e < BM * (BN / 8); e += T) {
            const int r = e >> 3, c = (e & 7) << 3;
            __half h8[8];
#pragma unroll
            for (int q = 0; q < 8; q++) {
                float v = sm.Cs[r][c + q];
                if (HAS_BIAS) v += bias[colBase + c + q];
                if (RELU) v = fmaxf(v, 0.f);
                h8[q] = __float2half(v);
            }
            *reinterpret_cast<int4*>(&C[(size_t)(rowBase + r) * N + colBase + c]) =
                *reinterpret_cast<int4*>(h8);
        }
    } else {
        // two-stage segment reduce: thread owns (row, 8-col segment)
#pragma unroll
        for (int e = tid; e < BM * 8; e += T) {
            const int r = e >> 3, sc = (e & 7) << 3;
            float v = 0.f;
#pragma unroll
            for (int i = 0; i < 8; i++) {
                const float h = fmaxf(sm.Cs[r][sc + i] + bs[sc + i], 0.f);
                v = fmaf(h, w3s[sc + i], v);
            }
            sp[r][sc >> 3] = v;
        }
        __syncthreads();
        for (int r = tid; r < BM; r += T) {
            float s = ((sp[r][0] + sp[r][1]) + (sp[r][2] + sp[r][3]))
                    + ((sp[r][4] + sp[r][5]) + (sp[r][6] + sp[r][7]));
            g_part[(size_t)blockIdx.x * M + rowBase + r] = s;
        }
    }
}

// ---------------------------------------------------------------------------
// Deterministic final reduce: out[i] = sum of 4 partials + b3.
// ---------------------------------------------------------------------------
__global__ void __launch_bounds__(256) reduce_kernel(const float* __restrict__ b3,
                                                     float* __restrict__ out)
{
    const int i = blockIdx.x * 256 + threadIdx.x;
    out[i] = ((g_part[i] + g_part[Bsz + i]) + (g_part[2 * Bsz + i] + g_part[3 * Bsz + i]))
             + b3[0];
}

// ---------------------------------------------------------------------------
extern "C" void kernel_launch(void* const* d_in, const int* in_sizes, int n_in,
                              void* d_out, int out_size)
{
    const int*   x    = (const int*)  d_in[0];
    const float* Wphi = (const float*)d_in[1];
    const float* bphi = (const float*)d_in[2];
    const float* W1   = (const float*)d_in[3];
    const float* b1   = (const float*)d_in[4];
    const float* W2   = (const float*)d_in[5];
    const float* b2   = (const float*)d_in[6];
    const float* W3   = (const float*)d_in[7];
    const float* b3   = (const float*)d_in[8];
    float* out = (float*)d_out;

    __half *hist_p, *u_p, *h1_p, *Wphi_p, *W1_p, *W2_p;
    float *b1eff_p;
    cudaGetSymbolAddress((void**)&hist_p,  g_hist);
    cudaGetSymbolAddress((void**)&u_p,     g_u);
    cudaGetSymbolAddress((void**)&h1_p,    g_h1);
    cudaGetSymbolAddress((void**)&Wphi_p,  g_Wphi);
    cudaGetSymbolAddress((void**)&W1_p,    g_W1);
    cudaGetSymbolAddress((void**)&W2_p,    g_W2);
    cudaGetSymbolAddress((void**)&b1eff_p, g_b1eff);

    // 0+1: histograms + weight conversion + b1_eff (independent block ranges)
    prep_kernel<<<512 + 64, 256>>>(x, Wphi, W1, W2, bphi, b1);

    // 2: u_c = hist @ W_phi            (4096x512)@(512x128)  BM=32 -> 256 blocks
    {
        dim3 grid(PHId / 64, Bsz / 32);
        gemm_tc<32, false, false, false><<<grid, 256>>>(hist_p, Wphi_p, nullptr, nullptr,
                                                        u_p, Bsz, PHId, Csz);
    }
    // 3: h1 = relu(u_c @ W1 + b1_eff)  (4096x128)@(128x512)  BM=64 -> 512 blocks
    {
        dim3 grid(H1d / 64, Bsz / 64);
        gemm_tc<64, true, true, false><<<grid, 256>>>(u_p, W1_p, b1eff_p, nullptr,
                                                      h1_p, Bsz, H1d, PHId);
    }
    // 4: fused h2 = relu(h1 @ W2 + b2); partials = h2 @ W3   BM=32 -> 512 blocks
    {
        dim3 grid(H2d / 64, Bsz / 32);
        gemm_tc<32, true, true, true><<<grid, 256>>>(h1_p, W2_p, b2, W3,
                                                     nullptr, Bsz, H2d, H1d);
    }
    // 5: deterministic reduce + b3
    reduce_kernel<<<Bsz / 256, 256>>>(b3, out);
}

// round 6
// speedup vs baseline: 1.1954x; 1.1954x over previous
#include <cuda_runtime.h>
#include <cuda_fp16.h>
#include <mma.h>

using namespace nvcuda;

#define Bsz  4096
#define Nseq 512
#define Csz  512
#define PHId 128
#define H1d  512
#define H2d  256

// Scratch (__device__ globals; no allocations allowed)
__device__ __half g_hist [Bsz * Csz];    // 4 MB   per-row label histogram (fp16, exact)
__device__ __half g_h1   [Bsz * H1d];    // 4 MB
__device__ float  g_part [4 * Bsz];      // partial dots (deterministic reduce)
__device__ __half g_Wc   [Csz * H1d];    // 512 KB  Wc = Wphi @ W1 (fp16)
__device__ __half g_W2   [H1d * H2d];
__device__ float  g_b1eff[H1d];          // b1 + 512 * (b_phi @ W1), exact fp32

// ---------------------------------------------------------------------------
// cp.async helpers (LDGSTS, 16B)
// ---------------------------------------------------------------------------
__device__ __forceinline__ void cp_async16(void* smem, const void* gmem) {
    unsigned s = (unsigned)__cvta_generic_to_shared(smem);
    asm volatile("cp.async.cg.shared.global [%0], [%1], 16;\n" :: "r"(s), "l"(gmem));
}
__device__ __forceinline__ void cp_commit() {
    asm volatile("cp.async.commit_group;\n");
}
template <int NN>
__device__ __forceinline__ void cp_wait() {
    asm volatile("cp.async.wait_group %0;\n" :: "n"(NN));
}

// ---------------------------------------------------------------------------
// Prep kernel, block ranges:
//   [0,512)   : per-row histograms (8 rows/block, smem atomics) -> g_hist fp16
//   [512,576) : Wc = Wphi @ W1  (fp32 compute, fp16 store), 64x64 tile/block
//   [576,608) : W2 fp32 -> fp16 convert
//   608       : b1_eff = b1 + 512*(b_phi @ W1) in fp32
// ---------------------------------------------------------------------------
__global__ void __launch_bounds__(256) prep_kernel(const int* __restrict__ x,
                                                   const float* __restrict__ Wphi,
                                                   const float* __restrict__ W1,
                                                   const float* __restrict__ W2,
                                                   const float* __restrict__ bphi,
                                                   const float* __restrict__ b1)
{
    __shared__ __align__(16) char praw[16384];   // 16 KB, aliased per branch
    const int tid = threadIdx.x;

    if (blockIdx.x < 512) {
        int* hs = reinterpret_cast<int*>(praw);  // [8][512]
#pragma unroll
        for (int i = 0; i < 16; i++) hs[tid + i * 256] = 0;
        __syncthreads();

        const int warp = tid >> 5, lane = tid & 31;
        const int row = blockIdx.x * 8 + warp;
        const int* xr = x + (size_t)row * Nseq;
#pragma unroll 4
        for (int j = lane; j < Nseq; j += 32) atomicAdd(&hs[warp * Csz + xr[j]], 1);
        __syncthreads();

#pragma unroll
        for (int e = tid; e < 8 * Csz; e += 256) {
            const int r = e >> 9, c = e & (Csz - 1);
            g_hist[(size_t)(blockIdx.x * 8 + r) * Csz + c] =
                __float2half((float)hs[r * Csz + c]);
        }
    } else if (blockIdx.x < 576) {
        // Wc tile: 64x64 outputs, K = 128 in 4 chunks of 32
        const int cb = blockIdx.x - 512;           // 0..63 -> 8x8 tiles
        const int tr = (cb >> 3) * 64, tcc = (cb & 7) * 64;
        float* sA = reinterpret_cast<float*>(praw);         // [64][32]
        float* sB = reinterpret_cast<float*>(praw + 8192);  // [32][64]
        const int ty = tid >> 4, tx = tid & 15;    // thread -> 4x4 outputs

        float acc[4][4];
#pragma unroll
        for (int i = 0; i < 4; i++)
#pragma unroll
            for (int j = 0; j < 4; j++) acc[i][j] = 0.f;

        for (int kc = 0; kc < 4; kc++) {
#pragma unroll
            for (int q = 0; q < 8; q++) {
                const int e = tid * 8 + q;         // A: 64x32
                sA[e] = Wphi[(size_t)(tr + (e >> 5)) * PHId + kc * 32 + (e & 31)];
            }
#pragma unroll
            for (int q = 0; q < 8; q++) {
                const int e = tid * 8 + q;         // B: 32x64
                sB[e] = W1[(size_t)(kc * 32 + (e >> 6)) * H1d + tcc + (e & 63)];
            }
            __syncthreads();
#pragma unroll
            for (int k = 0; k < 32; k++) {
                float a[4], b[4];
#pragma unroll
                for (int i = 0; i < 4; i++) a[i] = sA[(ty * 4 + i) * 32 + k];
#pragma unroll
                for (int j = 0; j < 4; j++) b[j] = sB[k * 64 + tx * 4 + j];
#pragma unroll
                for (int i = 0; i < 4; i++)
#pragma unroll
                    for (int j = 0; j < 4; j++) acc[i][j] = fmaf(a[i], b[j], acc[i][j]);
            }
            __syncthreads();
        }
#pragma unroll
        for (int i = 0; i < 4; i++)
#pragma unroll
            for (int j = 0; j < 4; j++)
                g_Wc[(size_t)(tr + ty * 4 + i) * H1d + tcc + tx * 4 + j] =
                    __float2half(acc[i][j]);
    } else if (blockIdx.x < 608) {
        const int cb = blockIdx.x - 576;           // 0..31
        const int t = cb * 256 + tid;
        for (int i = t; i < H1d * H2d; i += 32 * 256) g_W2[i] = __float2half(W2[i]);
    } else {
#pragma unroll
        for (int o = tid; o < H1d; o += 256) {
            float s = 0.f;
            for (int k = 0; k < PHId; k++) s = fmaf(bphi[k], W1[k * H1d + o], s);
            g_b1eff[o] = b1[o] + (float)Nseq * s;
        }
    }
}

// ---------------------------------------------------------------------------
// Pipelined fp16 tensor-core GEMM, fp32 accumulate, fused bias+ReLU epilogue.
// BM=64, BN=64, BK=64; 128 threads = 4 warps (2x2), warp tile 32x32
// (2 A-frags x 2 B-frags, fragment reuse). 2-stage cp.async pipeline,
// ONE __syncthreads per k-iteration (wait-before-sync pattern).
// FUSED: epilogue computes relu(acc+bias) dot W3-slice -> g_part.
// ---------------------------------------------------------------------------
template <bool FUSED>
__global__ void __launch_bounds__(128) gemm_tc(const __half* __restrict__ A,
                                               const __half* __restrict__ B,
                                               const float* __restrict__ bias,
                                               const float* __restrict__ W3,
                                               __half* __restrict__ C,
                                               int M, int N, int K)
{
    constexpr int BM = 64, BN = 64, BK = 64, T = 128;
    __shared__ __align__(16) union USM {
        struct { __half A[2][BM][BK + 8]; __half B[2][BK][BN + 8]; } in;   // 36 KB
        float Cs[BM][BN + 4];
    } sm;
    __shared__ float w3s[BN];
    __shared__ float bs[BN];
    __shared__ float sp[BM][2];

    const int tid  = threadIdx.x;
    const int warp = tid >> 5;
    const int wr   = warp & 1;      // row group: 32 rows
    const int wc   = warp >> 1;     // col group: 32 cols
    const int rowBase = blockIdx.y * BM;
    const int colBase = blockIdx.x * BN;

    if (FUSED && tid < BN) {
        w3s[tid] = W3[colBase + tid];
        bs[tid]  = bias[colBase + tid];
    }

    // loader map: 64 rows x 8 chunks(16B) = 512 chunks, 4 per thread
    const int lr = tid >> 3, lc = (tid & 7) << 3;

    auto load_tile = [&](int s, int kt) {
        const __half* Ak = A + (size_t)rowBase * K + kt * BK;
#pragma unroll
        for (int r = 0; r < 4; r++)
            cp_async16(&sm.in.A[s][lr + 16 * r][lc], Ak + (size_t)(lr + 16 * r) * K + lc);
        const __half* Bk = B + (size_t)(kt * BK) * N + colBase;
#pragma unroll
        for (int r = 0; r < 4; r++)
            cp_async16(&sm.in.B[s][lr + 16 * r][lc], Bk + (size_t)(lr + 16 * r) * N + lc);
    };

    wmma::fragment<wmma::accumulator, 16, 16, 16, float> acc[2][2];
#pragma unroll
    for (int i = 0; i < 2; i++)
#pragma unroll
        for (int j = 0; j < 2; j++) wmma::fill_fragment(acc[i][j], 0.f);

    const int KT = K / BK;
    load_tile(0, 0); cp_commit();

    for (int kt = 0; kt < KT; kt++) {
        cp_wait<0>();
        __syncthreads();             // all data of stage kt&1 visible; prev readers done
        if (kt + 1 < KT) load_tile((kt + 1) & 1, kt + 1);
        cp_commit();

        const int s = kt & 1;
#pragma unroll
        for (int kk = 0; kk < 4; kk++) {
            wmma::fragment<wmma::matrix_a, 16, 16, 16, __half, wmma::row_major> af[2];
            wmma::fragment<wmma::matrix_b, 16, 16, 16, __half, wmma::row_major> bf[2];
#pragma unroll
            for (int i = 0; i < 2; i++)
                wmma::load_matrix_sync(af[i], &sm.in.A[s][wr * 32 + i * 16][kk * 16], BK + 8);
#pragma unroll
            for (int j = 0; j < 2; j++)
                wmma::load_matrix_sync(bf[j], &sm.in.B[s][kk * 16][wc * 32 + j * 16], BN + 8);
#pragma unroll
            for (int i = 0; i < 2; i++)
#pragma unroll
                for (int j = 0; j < 2; j++)
                    wmma::mma_sync(acc[i][j], af[i], bf[j], acc[i][j]);
        }
    }
    __syncthreads();                 // before union re-use as Cs

    // spill accumulators to smem
#pragma unroll
    for (int i = 0; i < 2; i++)
#pragma unroll
        for (int j = 0; j < 2; j++)
            wmma::store_matrix_sync(&sm.Cs[wr * 32 + i * 16][wc * 32 + j * 16],
                                    acc[i][j], BN + 4, wmma::mem_row_major);
    __syncthreads();

    if (!FUSED) {
        // bias + relu + fp16 store, 8 cols/thread (STG.128), 4 iterations
#pragma unroll
        for (int e = tid; e < BM * (BN / 8); e += T) {
            const int r = e >> 3, c = (e & 7) << 3;
            __half h8[8];
#pragma unroll
            for (int q = 0; q < 8; q++) {
                float v = fmaxf(sm.Cs[r][c + q] + bias[colBase + c + q], 0.f);
                h8[q] = __float2half(v);
            }
            *reinterpret_cast<int4*>(&C[(size_t)(rowBase + r) * N + colBase + c]) =
                *reinterpret_cast<int4*>(h8);
        }
    } else {
        // thread -> (row, 32-col segment): 64 rows x 2 segs = 128 threads
        const int r = tid >> 1, sc = (tid & 1) << 5;
        float v = 0.f;
#pragma unroll
        for (int i = 0; i < 32; i++) {
            const float h = fmaxf(sm.Cs[r][sc + i] + bs[sc + i], 0.f);
            v = fmaf(h, w3s[sc + i], v);
        }
        sp[r][tid & 1] = v;
        __syncthreads();
        if (tid < BM)
            g_part[(size_t)blockIdx.x * M + rowBase + tid] = sp[tid][0] + sp[tid][1];
    }
}

// ---------------------------------------------------------------------------
// Deterministic final reduce: out[i] = sum of 4 partials + b3.
// ---------------------------------------------------------------------------
__global__ void __launch_bounds__(256) reduce_kernel(const float* __restrict__ b3,
                                                     float* __restrict__ out)
{
    const int i = blockIdx.x * 256 + threadIdx.x;
    out[i] = ((g_part[i] + g_part[Bsz + i]) + (g_part[2 * Bsz + i] + g_part[3 * Bsz + i]))
             + b3[0];
}

// ---------------------------------------------------------------------------
extern "C" void kernel_launch(void* const* d_in, const int* in_sizes, int n_in,
                              void* d_out, int out_size)
{
    const int*   x    = (const int*)  d_in[0];
    const float* Wphi = (const float*)d_in[1];
    const float* bphi = (const float*)d_in[2];
    const float* W1   = (const float*)d_in[3];
    const float* b1   = (const float*)d_in[4];
    const float* W2   = (const float*)d_in[5];
    const float* b2   = (const float*)d_in[6];
    const float* W3   = (const float*)d_in[7];
    const float* b3   = (const float*)d_in[8];
    float* out = (float*)d_out;

    __half *hist_p, *h1_p, *Wc_p, *W2_p;
    float *b1eff_p;
    cudaGetSymbolAddress((void**)&hist_p,  g_hist);
    cudaGetSymbolAddress((void**)&h1_p,    g_h1);
    cudaGetSymbolAddress((void**)&Wc_p,    g_Wc);
    cudaGetSymbolAddress((void**)&W2_p,    g_W2);
    cudaGetSymbolAddress((void**)&b1eff_p, g_b1eff);

    // 0: histograms + Wc = Wphi@W1 + W2 convert + b1_eff
    prep_kernel<<<609, 256>>>(x, Wphi, W1, W2, bphi, b1);

    // 1: h1 = relu(hist @ Wc + b1_eff)   (4096x512)@(512x512) -> 512 blocks
    {
        dim3 grid(H1d / 64, Bsz / 64);
        gemm_tc<false><<<grid, 128>>>(hist_p, Wc_p, b1eff_p, nullptr,
                                      h1_p, Bsz, H1d, Csz);
    }
    // 2: fused h2 = relu(h1 @ W2 + b2); partials = h2 @ W3 -> 256 blocks
    {
        dim3 grid(H2d / 64, Bsz / 64);
        gemm_tc<true><<<grid, 128>>>(h1_p, W2_p, b2, W3,
                                     nullptr, Bsz, H2d, H1d);
    }
    // 3: deterministic reduce + b3
    reduce_kernel<<<Bsz / 256, 256>>>(b3, out);
}